// round 16
// baseline (speedup 1.0000x reference)
#include <cuda_runtime.h>
#include <cuda_fp16.h>
#include <math.h>
#include <stdint.h>

#define N_SRC 100000
#define N_DST 50000
#define D_IN  128
#define D_OUT 64
#define BUCKET 128

#define TILES_Y 1563           // ceil(100000/64)
#define TILES_Z 782            // ceil(50000/64)
#define ASTR 136

// ---------------- scratch (device globals; no allocations allowed) ---------
__device__ __half g_yh[(size_t)N_SRC * D_OUT];     // fp16(x @ W_l)   12.8 MB
__device__ float  g_z[(size_t)N_DST * D_OUT];      // x[:N_DST]@W_r   12.8 MB
__device__ int    g_cnt[N_DST];                    // zero-init; gather re-zeroes
__device__ int    g_src[(size_t)N_DST * BUCKET];   // bucketed CSR    25.6 MB
// Pre-swizzled fp16 B fragments (exact ldmatrix register images), per type
__device__ uint4 g_bf[2][1024];                    // 32 KB

__device__ __forceinline__ uint32_t smem_u32(const void* p) {
    uint32_t a;
    asm("{ .reg .u64 t; cvta.to.shared.u64 t, %1; cvt.u32.u64 %0, t; }"
        : "=r"(a) : "l"(p));
    return a;
}

// ---------------------------------------------------------------------------
// prep: per-type (blockIdx.x: 0=W_l, 1=W_r) build fp16 W^T tile in smem, then
// warp 0 runs the gemm's exact b-ldmatrix pattern and stores the fragment
// registers to global. Never touches g_cnt/g_src (side stream owns those).
__global__ __launch_bounds__(256) void prep_kernel(const float* __restrict__ Wl,
                                                   const float* __restrict__ Wr) {
    extern __shared__ __align__(16) char psm[];
    __half* B = (__half*)psm;                          // 64 x 136
    int type = blockIdx.x;
    const float* W = type ? Wr : Wl;
    int tid = threadIdx.x;

    for (int i = tid; i < 64 * 128; i += 256) {
        int n = i >> 7, k = i & 127;
        B[n * ASTR + k] = __float2half_rn(W[k * 64 + n]);  // W^T[n][k]
    }
    __syncthreads();

    if (tid < 32) {
        int lane = tid;
        uint32_t bb = smem_u32(B);
        uint32_t boff = (((((lane >> 4) << 3) + (lane & 7)) * ASTR +
                         (((lane >> 3) & 1) << 3)) << 1);
        #pragma unroll
        for (int k = 0; k < 8; k++) {
            #pragma unroll
            for (int p = 0; p < 4; p++) {
                uint32_t po = ((p * ASTR) << 5) + (k << 5);
                uint32_t u0, u1, u2, u3;
                asm volatile("ldmatrix.sync.aligned.m8n8.x4.shared.b16 {%0,%1,%2,%3}, [%4];"
                             : "=r"(u0), "=r"(u1), "=r"(u2), "=r"(u3)
                             : "r"(bb + boff + po));
                g_bf[type][((k << 2) + p) * 32 + lane] = make_uint4(u0, u1, u2, u3);
            }
        }
    }
}
#define SM_PREP (64 * ASTR * 2)

// ---------------------------------------------------------------------------
__global__ void fill_kernel(const void* __restrict__ eiv, int n_edges) {
    const unsigned long long* q = (const unsigned long long*)eiv;
    bool is64 = (((q[0] | q[1] | q[2] | q[3]) >> 32) == 0ULL);

    int stride = gridDim.x * blockDim.x;
    for (int e = blockIdx.x * blockDim.x + threadIdx.x; e < n_edges; e += stride) {
        int s, d;
        if (is64) {
            const long long* ei = (const long long*)eiv;
            s = (int)ei[e];
            d = (int)ei[n_edges + e];
        } else {
            const int* ei = (const int*)eiv;
            s = ei[e];
            d = ei[n_edges + e];
        }
        int slot = atomicAdd(&g_cnt[d], 1);
        if (slot < BUCKET)
            g_src[(size_t)d * BUCKET + slot] = s;
    }
}

// ---------------------------------------------------------------------------
// Single-pass fp16 HMMA GEMM: 64x64 tile per CTA, 4 warps, 6 CTAs/SM.
// C(fp32) = half(A) @ half(W); B fragments pre-swizzled in global (L1-hot).
__global__ __launch_bounds__(128, 6) void gemm_mma_kernel(const float* __restrict__ x) {
    extern __shared__ __align__(16) char smem_raw[];
    __half* A = (__half*)smem_raw;                       // 64 x 136 fp16

    int tid = threadIdx.x, warp = tid >> 5, lane = tid & 31;

    int b = blockIdx.x;
    bool is_y;
    int row0, M;
    if (b < TILES_Y) { row0 = b << 6;             M = N_SRC; is_y = true;  }
    else             { row0 = (b - TILES_Y) << 6; M = N_DST; is_y = false; }
    const uint4* bf = g_bf[is_y ? 0 : 1];

    // Load x tile (64x128 fp32) -> fp16 smem
    #pragma unroll
    for (int i = tid; i < 64 * 32; i += 128) {
        int row = i >> 5, c4 = (i & 31) << 2;
        float4 v = make_float4(0.f, 0.f, 0.f, 0.f);
        if (row0 + row < M)
            v = *(const float4*)(x + (size_t)(row0 + row) * D_IN + c4);
        __half2 h01 = __floats2half2_rn(v.x, v.y);
        __half2 h23 = __floats2half2_rn(v.z, v.w);
        *(uint2*)(A + row * ASTR + c4) =
            make_uint2(*(uint32_t*)&h01, *(uint32_t*)&h23);
    }
    __syncthreads();

    int m0 = warp << 4;
    float c[8][4];
    #pragma unroll
    for (int n = 0; n < 8; n++)
        #pragma unroll
        for (int j = 0; j < 4; j++) c[n][j] = 0.f;

    uint32_t ab = smem_u32(A);
    uint32_t aoff = (((m0 + (lane & 15)) * ASTR + ((lane >> 4) << 3)) << 1);

    #pragma unroll
    for (int k = 0; k < 8; k++) {
        uint32_t x0, x1, x2, x3;
        asm volatile("ldmatrix.sync.aligned.m8n8.x4.shared.b16 {%0,%1,%2,%3}, [%4];"
                     : "=r"(x0), "=r"(x1), "=r"(x2), "=r"(x3)
                     : "r"(ab + aoff + (k << 5)));
        #pragma unroll
        for (int p = 0; p < 4; p++) {
            uint4 U = bf[((k << 2) + p) * 32 + lane];
            int n = p << 1;
            asm volatile(
                "mma.sync.aligned.m16n8k16.row.col.f32.f16.f16.f32 "
                "{%0,%1,%2,%3}, {%4,%5,%6,%7}, {%8,%9}, {%0,%1,%2,%3};"
                : "+f"(c[n][0]), "+f"(c[n][1]), "+f"(c[n][2]), "+f"(c[n][3])
                : "r"(x0), "r"(x1), "r"(x2), "r"(x3), "r"(U.x), "r"(U.y));
            asm volatile(
                "mma.sync.aligned.m16n8k16.row.col.f32.f16.f16.f32 "
                "{%0,%1,%2,%3}, {%4,%5,%6,%7}, {%8,%9}, {%0,%1,%2,%3};"
                : "+f"(c[n+1][0]), "+f"(c[n+1][1]), "+f"(c[n+1][2]), "+f"(c[n+1][3])
                : "r"(x0), "r"(x1), "r"(x2), "r"(x3), "r"(U.z), "r"(U.w));
        }
    }

    // Epilogue: c fragment (row gr=lane/4 [+8], cols n*8 + 2*(lane%4) +{0,1})
    int gr = lane >> 2, gc = (lane & 3) << 1;
    int r0 = row0 + m0 + gr;
    int r1 = r0 + 8;
    if (is_y) {
        #pragma unroll
        for (int n = 0; n < 8; n++) {
            int col = (n << 3) + gc;
            if (r0 < M)
                *(__half2*)(g_yh + (size_t)r0 * D_OUT + col) =
                    __floats2half2_rn(c[n][0], c[n][1]);
            if (r1 < M)
                *(__half2*)(g_yh + (size_t)r1 * D_OUT + col) =
                    __floats2half2_rn(c[n][2], c[n][3]);
        }
    } else {
        #pragma unroll
        for (int n = 0; n < 8; n++) {
            int col = (n << 3) + gc;
            if (r0 < M)
                *(float2*)(g_z + (size_t)r0 * D_OUT + col) = make_float2(c[n][0], c[n][1]);
            if (r1 < M)
                *(float2*)(g_z + (size_t)r1 * D_OUT + col) = make_float2(c[n][2], c[n][3]);
        }
    }
}
#define SM_GEMM (64 * ASTR * 2)

// ---------------------------------------------------------------------------
// Gather + finalize (R14/R15, measured 33.4-33.6us): one warp per dst row,
// 16 lanes per row (uint2 = 8B = cols 4l..4l+3), sub-half-warps alternate
// edges. 8 predicated independent LDG.64 in flight per lane => 16 edges/iter,
// MLP=8. Re-zeroes g_cnt[warp] at the end.
__global__ __launch_bounds__(256) void gather_finalize_kernel(
        float* __restrict__ out, const float* __restrict__ b_l) {
    int warp = (blockIdx.x * blockDim.x + threadIdx.x) >> 5;
    int lane = threadIdx.x & 31;
    if (warp >= N_DST) return;

    int cnt = g_cnt[warp];
    int n = cnt < BUCKET ? cnt : BUCKET;
    const int* bucket = g_src + (size_t)warp * BUCKET;
    int sub = lane >> 4, l = lane & 15;
    const uint2* yh2 = (const uint2*)g_yh + l;     // row r -> yh2[r*16]

    float a0 = 0.f, a1 = 0.f, a2 = 0.f, a3 = 0.f;
    uint2 zero2 = make_uint2(0u, 0u);
    for (int g = 0; g < n; g += 16) {
        int4 c0 = *(const int4*)(bucket + g);
        int4 c1 = *(const int4*)(bucket + g + 4);
        int4 c2 = *(const int4*)(bucket + g + 8);
        int4 c3 = *(const int4*)(bucket + g + 12);
        int s0 = sub ? c0.y : c0.x;
        int s1 = sub ? c0.w : c0.z;
        int s2 = sub ? c1.y : c1.x;
        int s3 = sub ? c1.w : c1.z;
        int s4 = sub ? c2.y : c2.x;
        int s5 = sub ? c2.w : c2.z;
        int s6 = sub ? c3.y : c3.x;
        int s7 = sub ? c3.w : c3.z;
        uint2 u0 = (g + 0  + sub < n) ? yh2[(size_t)s0 << 4] : zero2;
        uint2 u1 = (g + 2  + sub < n) ? yh2[(size_t)s1 << 4] : zero2;
        uint2 u2 = (g + 4  + sub < n) ? yh2[(size_t)s2 << 4] : zero2;
        uint2 u3 = (g + 6  + sub < n) ? yh2[(size_t)s3 << 4] : zero2;
        uint2 u4 = (g + 8  + sub < n) ? yh2[(size_t)s4 << 4] : zero2;
        uint2 u5 = (g + 10 + sub < n) ? yh2[(size_t)s5 << 4] : zero2;
        uint2 u6 = (g + 12 + sub < n) ? yh2[(size_t)s6 << 4] : zero2;
        uint2 u7 = (g + 14 + sub < n) ? yh2[(size_t)s7 << 4] : zero2;
        #define ACCUM(U)                                                        \
            { float2 fl = __half22float2(*(__half2*)&(U).x);                    \
              float2 fh = __half22float2(*(__half2*)&(U).y);                    \
              a0 += fl.x; a1 += fl.y; a2 += fh.x; a3 += fh.y; }
        ACCUM(u0); ACCUM(u1); ACCUM(u2); ACCUM(u3);
        ACCUM(u4); ACCUM(u5); ACCUM(u6); ACCUM(u7);
        #undef ACCUM
    }

    a0 += __shfl_xor_sync(0xffffffffu, a0, 16);
    a1 += __shfl_xor_sync(0xffffffffu, a1, 16);
    a2 += __shfl_xor_sync(0xffffffffu, a2, 16);
    a3 += __shfl_xor_sync(0xffffffffu, a3, 16);

    float inv = 1.0f / fmaxf((float)cnt, 1.0f);
    float4 zz = *(const float4*)(g_z + (size_t)warp * D_OUT + (l << 2));
    float4 bb = *(const float4*)(b_l + (l << 2));
    float v0 = a0 * inv + bb.x + zz.x;
    float v1 = a1 * inv + bb.y + zz.y;
    float v2 = a2 * inv + bb.z + zz.z;
    float v3 = a3 * inv + bb.w + zz.w;

    float m = fmaxf(fmaxf(v0, v1), fmaxf(v2, v3));
    #pragma unroll
    for (int o = 8; o; o >>= 1) m = fmaxf(m, __shfl_xor_sync(0xffffffffu, m, o));

    float s = __expf(v0 - m) + __expf(v1 - m) + __expf(v2 - m) + __expf(v3 - m);
    #pragma unroll
    for (int o = 8; o; o >>= 1) s += __shfl_xor_sync(0xffffffffu, s, o);

    float lz = m + __logf(s);
    if (sub == 0)
        *(float4*)(out + (size_t)warp * D_OUT + (l << 2)) =
            make_float4(v0 - lz, v1 - lz, v2 - lz, v3 - lz);

    if (lane == 0) g_cnt[warp] = 0;
}

// ---------------------------------------------------------------------------
extern "C" void kernel_launch(void* const* d_in, const int* in_sizes, int n_in,
                              void* d_out, int out_size) {
    const float* x  = (const float*)d_in[0];
    const float* Wl = (const float*)d_in[1];
    const float* bl = (const float*)d_in[2];
    const float* Wr = (const float*)d_in[3];
    const void*  ei = d_in[4];
    int n_edges = in_sizes[4] / 2;
    float* out = (float*)d_out;

    // One-time resources for the forked-stream graph topology (no device mem).
    static cudaStream_t side = nullptr;
    static cudaEvent_t ev_fork = nullptr, ev_join = nullptr;
    if (side == nullptr) {
        cudaStreamCreateWithFlags(&side, cudaStreamNonBlocking);
        cudaEventCreateWithFlags(&ev_fork, cudaEventDisableTiming);
        cudaEventCreateWithFlags(&ev_join, cudaEventDisableTiming);
        cudaFuncSetAttribute(prep_kernel,
                             cudaFuncAttributeMaxDynamicSharedMemorySize, SM_PREP);
        cudaFuncSetAttribute(gemm_mma_kernel,
                             cudaFuncAttributeMaxDynamicSharedMemorySize, SM_GEMM);
    }

    // Fork: CSR build (atomic/L2-bound) runs alongside prep + GEMM
    // (tensor/latency-bound). Side stream exclusively owns g_cnt/g_src until
    // ev_join; counters arrive zeroed (gather re-zeroed them last replay).
    cudaEventRecord(ev_fork, 0);
    cudaStreamWaitEvent(side, ev_fork, 0);
    fill_kernel<<<2048, 256, 0, side>>>(ei, n_edges);
    cudaEventRecord(ev_join, side);

    // Main stream: W fragment prepack, then tensor-core projections.
    prep_kernel<<<2, 256, SM_PREP>>>(Wl, Wr);
    gemm_mma_kernel<<<TILES_Y + TILES_Z, 128, SM_GEMM>>>(x);

    // Join, then gather + finalize.
    cudaStreamWaitEvent(0, ev_join, 0);
    gather_finalize_kernel<<<(N_DST * 32 + 255) / 256, 256>>>(out, bl);
}

// round 17
// speedup vs baseline: 1.0256x; 1.0256x over previous
#include <cuda_runtime.h>
#include <cuda_fp16.h>
#include <math.h>
#include <stdint.h>

#define N_SRC 100000
#define N_DST 50000
#define D_IN  128
#define D_OUT 64
#define BUCKET 128

#define TILES_Y 1563           // ceil(100000/64) — one fused CTA per x-tile
#define ASTR 136

// ---------------- scratch (device globals; no allocations allowed) ---------
__device__ __half g_yh[(size_t)N_SRC * D_OUT];     // fp16(x @ W_l)   12.8 MB
__device__ float  g_z[(size_t)N_DST * D_OUT];      // x[:N_DST]@W_r   12.8 MB
__device__ int    g_cnt[N_DST];                    // zero-init; gather re-zeroes
__device__ int    g_src[(size_t)N_DST * BUCKET];   // bucketed CSR    25.6 MB
// Pre-swizzled fp16 B fragments (exact ldmatrix register images), per type
__device__ uint4 g_bf[2][1024];                    // 32 KB

__device__ __forceinline__ uint32_t smem_u32(const void* p) {
    uint32_t a;
    asm("{ .reg .u64 t; cvta.to.shared.u64 t, %1; cvt.u32.u64 %0, t; }"
        : "=r"(a) : "l"(p));
    return a;
}

// ---------------------------------------------------------------------------
// prep: per-type (blockIdx.x: 0=W_l, 1=W_r) build fp16 W^T tile in smem, then
// warp 0 runs the gemm's exact b-ldmatrix pattern and stores the fragment
// registers to global. Never touches g_cnt/g_src (side stream owns those).
__global__ __launch_bounds__(256) void prep_kernel(const float* __restrict__ Wl,
                                                   const float* __restrict__ Wr) {
    extern __shared__ __align__(16) char psm[];
    __half* B = (__half*)psm;                          // 64 x 136
    int type = blockIdx.x;
    const float* W = type ? Wr : Wl;
    int tid = threadIdx.x;

    for (int i = tid; i < 64 * 128; i += 256) {
        int n = i >> 7, k = i & 127;
        B[n * ASTR + k] = __float2half_rn(W[k * 64 + n]);  // W^T[n][k]
    }
    __syncthreads();

    if (tid < 32) {
        int lane = tid;
        uint32_t bb = smem_u32(B);
        uint32_t boff = (((((lane >> 4) << 3) + (lane & 7)) * ASTR +
                         (((lane >> 3) & 1) << 3)) << 1);
        #pragma unroll
        for (int k = 0; k < 8; k++) {
            #pragma unroll
            for (int p = 0; p < 4; p++) {
                uint32_t po = ((p * ASTR) << 5) + (k << 5);
                uint32_t u0, u1, u2, u3;
                asm volatile("ldmatrix.sync.aligned.m8n8.x4.shared.b16 {%0,%1,%2,%3}, [%4];"
                             : "=r"(u0), "=r"(u1), "=r"(u2), "=r"(u3)
                             : "r"(bb + boff + po));
                g_bf[type][((k << 2) + p) * 32 + lane] = make_uint4(u0, u1, u2, u3);
            }
        }
    }
}
#define SM_PREP (64 * ASTR * 2)

// ---------------------------------------------------------------------------
__global__ void fill_kernel(const void* __restrict__ eiv, int n_edges) {
    const unsigned long long* q = (const unsigned long long*)eiv;
    bool is64 = (((q[0] | q[1] | q[2] | q[3]) >> 32) == 0ULL);

    int stride = gridDim.x * blockDim.x;
    for (int e = blockIdx.x * blockDim.x + threadIdx.x; e < n_edges; e += stride) {
        int s, d;
        if (is64) {
            const long long* ei = (const long long*)eiv;
            s = (int)ei[e];
            d = (int)ei[n_edges + e];
        } else {
            const int* ei = (const int*)eiv;
            s = ei[e];
            d = ei[n_edges + e];
        }
        int slot = atomicAdd(&g_cnt[d], 1);
        if (slot < BUCKET)
            g_src[(size_t)d * BUCKET + slot] = s;
    }
}

// ---------------------------------------------------------------------------
// Fused fp16 HMMA GEMM: ONE 64-row x-tile per CTA (x read exactly once).
// 8 warps share the A smem tile: warps 0-3 compute y = x@W_l (all tiles),
// warps 4-7 compute z = x@W_r (only tiles with row0 < N_DST).
__global__ __launch_bounds__(256, 3) void gemm_mma_kernel(const float* __restrict__ x) {
    extern __shared__ __align__(16) char smem_raw[];
    __half* A = (__half*)smem_raw;                       // 64 x 136 fp16

    int tid = threadIdx.x, warp = tid >> 5, lane = tid & 31;
    int row0 = blockIdx.x << 6;

    // Load x tile (64x128 fp32) -> fp16 smem, all 256 threads
    #pragma unroll
    for (int i = tid; i < 64 * 32; i += 256) {
        int row = i >> 5, c4 = (i & 31) << 2;
        float4 v = make_float4(0.f, 0.f, 0.f, 0.f);
        if (row0 + row < N_SRC)
            v = *(const float4*)(x + (size_t)(row0 + row) * D_IN + c4);
        __half2 h01 = __floats2half2_rn(v.x, v.y);
        __half2 h23 = __floats2half2_rn(v.z, v.w);
        *(uint2*)(A + row * ASTR + c4) =
            make_uint2(*(uint32_t*)&h01, *(uint32_t*)&h23);
    }
    __syncthreads();

    bool do_z = (warp >= 4);
    if (do_z && row0 >= N_DST) return;       // no z rows in this tile
    const uint4* bf = g_bf[do_z ? 1 : 0];

    int m0 = (warp & 3) << 4;
    float c[8][4];
    #pragma unroll
    for (int n = 0; n < 8; n++)
        #pragma unroll
        for (int j = 0; j < 4; j++) c[n][j] = 0.f;

    uint32_t ab = smem_u32(A);
    uint32_t aoff = (((m0 + (lane & 15)) * ASTR + ((lane >> 4) << 3)) << 1);

    #pragma unroll
    for (int k = 0; k < 8; k++) {
        uint32_t x0, x1, x2, x3;
        asm volatile("ldmatrix.sync.aligned.m8n8.x4.shared.b16 {%0,%1,%2,%3}, [%4];"
                     : "=r"(x0), "=r"(x1), "=r"(x2), "=r"(x3)
                     : "r"(ab + aoff + (k << 5)));
        #pragma unroll
        for (int p = 0; p < 4; p++) {
            uint4 U = bf[((k << 2) + p) * 32 + lane];
            int n = p << 1;
            asm volatile(
                "mma.sync.aligned.m16n8k16.row.col.f32.f16.f16.f32 "
                "{%0,%1,%2,%3}, {%4,%5,%6,%7}, {%8,%9}, {%0,%1,%2,%3};"
                : "+f"(c[n][0]), "+f"(c[n][1]), "+f"(c[n][2]), "+f"(c[n][3])
                : "r"(x0), "r"(x1), "r"(x2), "r"(x3), "r"(U.x), "r"(U.y));
            asm volatile(
                "mma.sync.aligned.m16n8k16.row.col.f32.f16.f16.f32 "
                "{%0,%1,%2,%3}, {%4,%5,%6,%7}, {%8,%9}, {%0,%1,%2,%3};"
                : "+f"(c[n+1][0]), "+f"(c[n+1][1]), "+f"(c[n+1][2]), "+f"(c[n+1][3])
                : "r"(x0), "r"(x1), "r"(x2), "r"(x3), "r"(U.z), "r"(U.w));
        }
    }

    // Epilogue: c fragment (row gr=lane/4 [+8], cols n*8 + 2*(lane%4) +{0,1})
    int gr = lane >> 2, gc = (lane & 3) << 1;
    int r0 = row0 + m0 + gr;
    int r1 = r0 + 8;
    if (!do_z) {
        #pragma unroll
        for (int n = 0; n < 8; n++) {
            int col = (n << 3) + gc;
            if (r0 < N_SRC)
                *(__half2*)(g_yh + (size_t)r0 * D_OUT + col) =
                    __floats2half2_rn(c[n][0], c[n][1]);
            if (r1 < N_SRC)
                *(__half2*)(g_yh + (size_t)r1 * D_OUT + col) =
                    __floats2half2_rn(c[n][2], c[n][3]);
        }
    } else {
        #pragma unroll
        for (int n = 0; n < 8; n++) {
            int col = (n << 3) + gc;
            if (r0 < N_DST)
                *(float2*)(g_z + (size_t)r0 * D_OUT + col) = make_float2(c[n][0], c[n][1]);
            if (r1 < N_DST)
                *(float2*)(g_z + (size_t)r1 * D_OUT + col) = make_float2(c[n][2], c[n][3]);
        }
    }
}
#define SM_GEMM (64 * ASTR * 2)

// ---------------------------------------------------------------------------
// Gather + finalize (R14/R15, measured 33.4-33.6us): one warp per dst row,
// 16 lanes per row (uint2 = 8B = cols 4l..4l+3), sub-half-warps alternate
// edges. 8 predicated independent LDG.64 in flight per lane => 16 edges/iter,
// MLP=8. Re-zeroes g_cnt[warp] at the end.
__global__ __launch_bounds__(256) void gather_finalize_kernel(
        float* __restrict__ out, const float* __restrict__ b_l) {
    int warp = (blockIdx.x * blockDim.x + threadIdx.x) >> 5;
    int lane = threadIdx.x & 31;
    if (warp >= N_DST) return;

    int cnt = g_cnt[warp];
    int n = cnt < BUCKET ? cnt : BUCKET;
    const int* bucket = g_src + (size_t)warp * BUCKET;
    int sub = lane >> 4, l = lane & 15;
    const uint2* yh2 = (const uint2*)g_yh + l;     // row r -> yh2[r*16]

    float a0 = 0.f, a1 = 0.f, a2 = 0.f, a3 = 0.f;
    uint2 zero2 = make_uint2(0u, 0u);
    for (int g = 0; g < n; g += 16) {
        int4 c0 = *(const int4*)(bucket + g);
        int4 c1 = *(const int4*)(bucket + g + 4);
        int4 c2 = *(const int4*)(bucket + g + 8);
        int4 c3 = *(const int4*)(bucket + g + 12);
        int s0 = sub ? c0.y : c0.x;
        int s1 = sub ? c0.w : c0.z;
        int s2 = sub ? c1.y : c1.x;
        int s3 = sub ? c1.w : c1.z;
        int s4 = sub ? c2.y : c2.x;
        int s5 = sub ? c2.w : c2.z;
        int s6 = sub ? c3.y : c3.x;
        int s7 = sub ? c3.w : c3.z;
        uint2 u0 = (g + 0  + sub < n) ? yh2[(size_t)s0 << 4] : zero2;
        uint2 u1 = (g + 2  + sub < n) ? yh2[(size_t)s1 << 4] : zero2;
        uint2 u2 = (g + 4  + sub < n) ? yh2[(size_t)s2 << 4] : zero2;
        uint2 u3 = (g + 6  + sub < n) ? yh2[(size_t)s3 << 4] : zero2;
        uint2 u4 = (g + 8  + sub < n) ? yh2[(size_t)s4 << 4] : zero2;
        uint2 u5 = (g + 10 + sub < n) ? yh2[(size_t)s5 << 4] : zero2;
        uint2 u6 = (g + 12 + sub < n) ? yh2[(size_t)s6 << 4] : zero2;
        uint2 u7 = (g + 14 + sub < n) ? yh2[(size_t)s7 << 4] : zero2;
        #define ACCUM(U)                                                        \
            { float2 fl = __half22float2(*(__half2*)&(U).x);                    \
              float2 fh = __half22float2(*(__half2*)&(U).y);                    \
              a0 += fl.x; a1 += fl.y; a2 += fh.x; a3 += fh.y; }
        ACCUM(u0); ACCUM(u1); ACCUM(u2); ACCUM(u3);
        ACCUM(u4); ACCUM(u5); ACCUM(u6); ACCUM(u7);
        #undef ACCUM
    }

    a0 += __shfl_xor_sync(0xffffffffu, a0, 16);
    a1 += __shfl_xor_sync(0xffffffffu, a1, 16);
    a2 += __shfl_xor_sync(0xffffffffu, a2, 16);
    a3 += __shfl_xor_sync(0xffffffffu, a3, 16);

    float inv = 1.0f / fmaxf((float)cnt, 1.0f);
    float4 zz = *(const float4*)(g_z + (size_t)warp * D_OUT + (l << 2));
    float4 bb = *(const float4*)(b_l + (l << 2));
    float v0 = a0 * inv + bb.x + zz.x;
    float v1 = a1 * inv + bb.y + zz.y;
    float v2 = a2 * inv + bb.z + zz.z;
    float v3 = a3 * inv + bb.w + zz.w;

    float m = fmaxf(fmaxf(v0, v1), fmaxf(v2, v3));
    #pragma unroll
    for (int o = 8; o; o >>= 1) m = fmaxf(m, __shfl_xor_sync(0xffffffffu, m, o));

    float s = __expf(v0 - m) + __expf(v1 - m) + __expf(v2 - m) + __expf(v3 - m);
    #pragma unroll
    for (int o = 8; o; o >>= 1) s += __shfl_xor_sync(0xffffffffu, s, o);

    float lz = m + __logf(s);
    if (sub == 0)
        *(float4*)(out + (size_t)warp * D_OUT + (l << 2)) =
            make_float4(v0 - lz, v1 - lz, v2 - lz, v3 - lz);

    if (lane == 0) g_cnt[warp] = 0;
}

// ---------------------------------------------------------------------------
extern "C" void kernel_launch(void* const* d_in, const int* in_sizes, int n_in,
                              void* d_out, int out_size) {
    const float* x  = (const float*)d_in[0];
    const float* Wl = (const float*)d_in[1];
    const float* bl = (const float*)d_in[2];
    const float* Wr = (const float*)d_in[3];
    const void*  ei = d_in[4];
    int n_edges = in_sizes[4] / 2;
    float* out = (float*)d_out;

    // One-time resources for the forked-stream graph topology (no device mem).
    static cudaStream_t side = nullptr;
    static cudaEvent_t ev_fork = nullptr, ev_join = nullptr;
    if (side == nullptr) {
        cudaStreamCreateWithFlags(&side, cudaStreamNonBlocking);
        cudaEventCreateWithFlags(&ev_fork, cudaEventDisableTiming);
        cudaEventCreateWithFlags(&ev_join, cudaEventDisableTiming);
        cudaFuncSetAttribute(prep_kernel,
                             cudaFuncAttributeMaxDynamicSharedMemorySize, SM_PREP);
        cudaFuncSetAttribute(gemm_mma_kernel,
                             cudaFuncAttributeMaxDynamicSharedMemorySize, SM_GEMM);
    }

    // Fork: CSR build runs alongside prep + GEMM (side stream exclusively
    // owns g_cnt/g_src until ev_join; counters arrive zeroed).
    cudaEventRecord(ev_fork, 0);
    cudaStreamWaitEvent(side, ev_fork, 0);
    fill_kernel<<<2048, 256, 0, side>>>(ei, n_edges);
    cudaEventRecord(ev_join, side);

    // Main stream: W fragment prepack, then fused y+z tensor-core projection.
    prep_kernel<<<2, 256, SM_PREP>>>(Wl, Wr);
    gemm_mma_kernel<<<TILES_Y, 256, SM_GEMM>>>(x);

    // Join, then gather + finalize.
    cudaStreamWaitEvent(0, ev_join, 0);
    gather_finalize_kernel<<<(N_DST * 32 + 255) / 256, 256>>>(out, bl);
}